// round 1
// baseline (speedup 1.0000x reference)
#include <cuda_runtime.h>
#include <cuda_bf16.h>

// ---------------- problem constants ----------------
#define TT 8
#define BB 32
#define C1 128          // channels after conv1/conv2
#define H1 48
#define P1S 24          // after pool1
#define P2S 12          // after pool2
#define FC1_IN  (128*12*12)   // 18432
#define FC1_OUT 1152
#define FC2_OUT 128
#define FC3_OUT 7
#define NROWS (TT*BB)   // 256 "batch" rows for the FC stage

// ---------------- scratch (static device memory, no allocs) ----------------
__device__ unsigned char g_p1[TT*BB*C1*P1S*P1S];          // 18.9 MB spikes after pool1
__device__ float g_p2[TT*BB*C1*P2S*P2S];                  // 18.9 MB spikes after pool2 (float for GEMM)
__device__ float g_part1[8*NROWS*FC1_OUT];                // split-K partials for fc1
__device__ float g_a1[NROWS*FC1_OUT];
__device__ float g_l1[NROWS*FC1_OUT];
__device__ float g_part2[NROWS*FC2_OUT];
__device__ float g_a2[NROWS*FC2_OUT];
__device__ float g_l2[NROWS*FC2_OUT];

// ============================================================
// Kernel 1: conv1 (1->128, 3x3 SAME) + BN1 + IF over T + maxpool 2x2
// One thread per (b, c, pooled y, pooled x). Input broadcast over T,
// so the IF recurrence is a register loop; writes uint8 spikes.
// ============================================================
__global__ void k_conv1_if_pool(const float* __restrict__ x,
                                const float* __restrict__ w1,
                                const float* __restrict__ b1,
                                const float* __restrict__ bg,
                                const float* __restrict__ bbta,
                                const float* __restrict__ bm,
                                const float* __restrict__ bv)
{
    int idx = blockIdx.x * blockDim.x + threadIdx.x;
    if (idx >= BB*C1*P1S*P1S) return;
    int p  = idx % (P1S*P1S);
    int c  = (idx / (P1S*P1S)) % C1;
    int b  = idx / (P1S*P1S*C1);
    int py = p / P1S, px = p % P1S;

    float w[9];
#pragma unroll
    for (int k = 0; k < 9; k++) w[k] = w1[c*9 + k];
    float scale = bg[c] * rsqrtf(bv[c] + 1e-5f);
    float add   = (b1[c] - bm[c]) * scale + bbta[c];

    const float* xb = x + b*H1*H1;
    float h[4];
#pragma unroll
    for (int d = 0; d < 4; d++) {
        int y  = 2*py + (d >> 1);
        int xx = 2*px + (d & 1);
        float s = 0.f;
#pragma unroll
        for (int ky = 0; ky < 3; ky++) {
            int gy = y + ky - 1;
            if (gy < 0 || gy >= H1) continue;
#pragma unroll
            for (int kx = 0; kx < 3; kx++) {
                int gx = xx + kx - 1;
                if (gx < 0 || gx >= H1) continue;
                s += xb[gy*H1 + gx] * w[ky*3 + kx];
            }
        }
        h[d] = s * scale + add;
    }

    float v[4] = {0.f, 0.f, 0.f, 0.f};
#pragma unroll
    for (int t = 0; t < TT; t++) {
        unsigned char any = 0;
#pragma unroll
        for (int d = 0; d < 4; d++) {
            v[d] += h[d];
            if (v[d] >= 1.0f) { any = 1; v[d] = 0.f; }
        }
        g_p1[((t*BB + b)*C1 + c)*(P1S*P1S) + p] = any;
    }
}

// ============================================================
// Kernel 2: conv2 (128->128, 3x3 SAME on 24x24) + BN2 + IF over T + maxpool
// Block: 256 threads = 32 oc-lanes x 8 quad-slots.
// Each thread owns one 2x2 output quad (= one pooled output) for ALL 8
// timesteps -> 32 fp32 accumulators; weights reused across t; the IF
// recurrence + pool run in registers. grid = (18 spatial tiles, 4 oc tiles, 32 b).
// ============================================================
__global__ void __launch_bounds__(256)
k_conv2_if_pool(const float* __restrict__ w2,
                const float* __restrict__ b2,
                const float* __restrict__ bg,
                const float* __restrict__ bbta,
                const float* __restrict__ bm,
                const float* __restrict__ bv)
{
    __shared__ float in_s[TT*8*6*10];   // [t][ic(8)][row 6][col 10] = 3840 floats
    __shared__ float w_s[72*33];        // [(ic*9+k)*33 + oc] padded vs bank conflicts

    int tid  = threadIdx.x;
    int oc_l = tid & 31;
    int slot = tid >> 5;
    int qtx = blockIdx.x % 3;          // 4 quads wide  -> 8 cols at s2 level
    int qty = blockIdx.x / 3;          // 2 quads tall  -> 4 rows at s2 level
    int b   = blockIdx.z;
    int oc  = blockIdx.y * 32 + oc_l;
    int sx = slot & 3, sy = slot >> 2;

    float acc[32];
#pragma unroll
    for (int i = 0; i < 32; i++) acc[i] = 0.f;

    int gy0 = qty*4 - 1;
    int gx0 = qtx*8 - 1;

    for (int ch = 0; ch < 16; ch++) {
        int ic0 = ch * 8;
        // ---- stage input spikes (uint8 -> float, zero-padded halo) ----
        for (int e = tid; e < TT*8*60; e += 256) {
            int t  = e / 480;
            int r  = e % 480;
            int ic = r / 60;
            int rr = r % 60;
            int ry = rr / 10, rx = rr % 10;
            int gy = gy0 + ry, gx = gx0 + rx;
            float val = 0.f;
            if ((unsigned)gy < (unsigned)P1S && (unsigned)gx < (unsigned)P1S)
                val = (float)g_p1[((t*BB + b)*C1 + ic0 + ic)*(P1S*P1S) + gy*P1S + gx];
            in_s[e] = val;
        }
        // ---- stage weights, transposed so compute loads are conflict-free ----
        for (int e = tid; e < 32*72; e += 256) {
            int o = e / 72;
            int r = e % 72;                 // ic*9 + k
            w_s[r*33 + o] = w2[((blockIdx.y*32 + o)*C1 + ic0 + r/9)*9 + (r % 9)];
        }
        __syncthreads();

#pragma unroll
        for (int ic = 0; ic < 8; ic++) {
            float wk[9];
#pragma unroll
            for (int k = 0; k < 9; k++) wk[k] = w_s[(ic*9 + k)*33 + oc_l];
#pragma unroll
            for (int t = 0; t < TT; t++) {
                const float* base = &in_s[((t*8 + ic)*6 + sy*2)*10 + sx*2];
                float pin[4][4];
#pragma unroll
                for (int ry = 0; ry < 4; ry++)
#pragma unroll
                    for (int rx = 0; rx < 4; rx++)
                        pin[ry][rx] = base[ry*10 + rx];
#pragma unroll
                for (int py = 0; py < 2; py++)
#pragma unroll
                    for (int px = 0; px < 2; px++) {
                        float s = acc[t*4 + py*2 + px];
#pragma unroll
                        for (int ky = 0; ky < 3; ky++)
#pragma unroll
                            for (int kx = 0; kx < 3; kx++)
                                s += wk[ky*3 + kx] * pin[py + ky][px + kx];
                        acc[t*4 + py*2 + px] = s;
                    }
            }
        }
        __syncthreads();
    }

    // BN2 + IF over T + 2x2 max pool (OR of binary spikes)
    float scale = bg[oc] * rsqrtf(bv[oc] + 1e-5f);
    float add   = (b2[oc] - bm[oc]) * scale + bbta[oc];
    float v[4] = {0.f, 0.f, 0.f, 0.f};
    int qx = qtx*4 + sx;
    int qy = qty*2 + sy;
#pragma unroll
    for (int t = 0; t < TT; t++) {
        float any = 0.f;
#pragma unroll
        for (int d = 0; d < 4; d++) {
            v[d] += acc[t*4 + d] * scale + add;
            if (v[d] >= 1.0f) { any = 1.f; v[d] = 0.f; }
        }
        g_p2[((t*BB + b)*C1 + oc)*(P2S*P2S) + qy*P2S + qx] = any;
    }
}

// ============================================================
// Generic tiled GEMM: P[z] tile = A[64 rows, K] * B[64 rows, K]^T
// (C = A * B^T), deterministic split-K via blockIdx.z partial slices.
// which==0: A=g_p2   (fc1 input), P=g_part1
// which==1: A=g_l1   (fc2 input), P=g_part2
// ============================================================
__global__ void __launch_bounds__(256)
k_gemm(const float* __restrict__ Bmat, int which, int N, int K, int klen)
{
    __shared__ float As[64][17];
    __shared__ float Bs[64][17];
    const float* A = (which == 0) ? g_p2 : g_l1;
    float* P       = (which == 0) ? g_part1 : g_part2;

    int tid = threadIdx.x;
    int tx = tid & 15, ty = tid >> 4;
    int bm = blockIdx.y, bn = blockIdx.x, sz = blockIdx.z;
    int ks = sz * klen;
    int ke = ks + klen;

    float acc[4][4];
#pragma unroll
    for (int i = 0; i < 4; i++)
#pragma unroll
        for (int j = 0; j < 4; j++) acc[i][j] = 0.f;

    for (int kk = ks; kk < ke; kk += 16) {
#pragma unroll
        for (int l = 0; l < 4; l++) {
            int e = tid + l*256;
            int row = e >> 4, col = e & 15;
            As[row][col] = A[(bm*64 + row)*K + kk + col];
            Bs[row][col] = Bmat[(bn*64 + row)*K + kk + col];
        }
        __syncthreads();
#pragma unroll
        for (int c = 0; c < 16; c++) {
            float a[4], bv[4];
#pragma unroll
            for (int i = 0; i < 4; i++) a[i] = As[ty*4 + i][c];
#pragma unroll
            for (int j = 0; j < 4; j++) bv[j] = Bs[tx*4 + j][c];
#pragma unroll
            for (int i = 0; i < 4; i++)
#pragma unroll
                for (int j = 0; j < 4; j++) acc[i][j] += a[i] * bv[j];
        }
        __syncthreads();
    }
#pragma unroll
    for (int i = 0; i < 4; i++)
#pragma unroll
        for (int j = 0; j < 4; j++)
            P[(size_t)sz*NROWS*N + (bm*64 + ty*4 + i)*N + bn*64 + tx*4 + j] = acc[i][j];
}

// Deterministic split-K reduction + bias
__global__ void k_reduce_bias(const float* __restrict__ bias, int which, int N, int S)
{
    const float* P = (which == 0) ? g_part1 : g_part2;
    float* C       = (which == 0) ? g_a1 : g_a2;
    int idx = blockIdx.x * blockDim.x + threadIdx.x;
    if (idx >= NROWS*N) return;
    float s = bias[idx % N];
    for (int z = 0; z < S; z++) s += P[(size_t)z*NROWS*N + idx];
    C[idx] = s;
}

// LIF over T (tau=2, vth=1, hard reset). A,L are [T*B][N] n-major.
__global__ void k_lif(int which, int N)
{
    const float* A = (which == 0) ? g_a1 : g_a2;
    float* L       = (which == 0) ? g_l1 : g_l2;
    int idx = blockIdx.x * blockDim.x + threadIdx.x;
    if (idx >= BB*N) return;
    int b = idx / N, o = idx % N;
    float v = 0.f;
#pragma unroll
    for (int t = 0; t < TT; t++) {
        float x = A[(t*BB + b)*N + o];
        v += (x - v) * 0.5f;
        float s = (v >= 1.0f) ? 1.f : 0.f;
        L[(t*BB + b)*N + o] = s;
        if (s != 0.f) v = 0.f;
    }
}

// fc3 (128->7) + LIF + mean over T, fused. grid = 32 (b), block = 32.
__global__ void k_fc3_lif_mean(const float* __restrict__ w,
                               const float* __restrict__ bias,
                               float* __restrict__ out)
{
    __shared__ float row[FC2_OUT];
    int b = blockIdx.x, tid = threadIdx.x;
    float v = 0.f, acc = 0.f;
#pragma unroll
    for (int t = 0; t < TT; t++) {
        for (int i = tid; i < FC2_OUT; i += 32)
            row[i] = g_l2[(t*BB + b)*FC2_OUT + i];
        __syncthreads();
        if (tid < FC3_OUT) {
            float s = bias[tid];
#pragma unroll 8
            for (int i = 0; i < FC2_OUT; i++) s += row[i] * w[tid*FC2_OUT + i];
            v += (s - v) * 0.5f;
            if (v >= 1.0f) { acc += 1.f; v = 0.f; }
        }
        __syncthreads();
    }
    if (tid < FC3_OUT) out[b*FC3_OUT + tid] = acc * 0.125f;
}

// ============================================================
extern "C" void kernel_launch(void* const* d_in, const int* in_sizes, int n_in,
                              void* d_out, int out_size)
{
    const float* x       = (const float*)d_in[0];
    const float* conv1_w = (const float*)d_in[1];
    const float* conv1_b = (const float*)d_in[2];
    const float* bn1_g   = (const float*)d_in[3];
    const float* bn1_b   = (const float*)d_in[4];
    const float* bn1_m   = (const float*)d_in[5];
    const float* bn1_v   = (const float*)d_in[6];
    const float* conv2_w = (const float*)d_in[7];
    const float* conv2_b = (const float*)d_in[8];
    const float* bn2_g   = (const float*)d_in[9];
    const float* bn2_b   = (const float*)d_in[10];
    const float* bn2_m   = (const float*)d_in[11];
    const float* bn2_v   = (const float*)d_in[12];
    const float* fc1_w   = (const float*)d_in[13];
    const float* fc1_b   = (const float*)d_in[14];
    const float* fc2_w   = (const float*)d_in[15];
    const float* fc2_b   = (const float*)d_in[16];
    const float* fc3_w   = (const float*)d_in[17];
    const float* fc3_b   = (const float*)d_in[18];
    float* out = (float*)d_out;

    // 1) conv1 + BN1 + IF + pool  -> g_p1 (uint8 spikes)
    {
        int total = BB*C1*P1S*P1S;
        k_conv1_if_pool<<<(total + 255)/256, 256>>>(x, conv1_w, conv1_b,
                                                    bn1_g, bn1_b, bn1_m, bn1_v);
    }
    // 2) conv2 + BN2 + IF + pool  -> g_p2 (float spikes)
    {
        dim3 grid(18, 4, BB);
        k_conv2_if_pool<<<grid, 256>>>(conv2_w, conv2_b, bn2_g, bn2_b, bn2_m, bn2_v);
    }
    // 3) fc1 GEMM (split-K=8) + reduce + LIF
    {
        dim3 grid(FC1_OUT/64, NROWS/64, 8);
        k_gemm<<<grid, 256>>>(fc1_w, 0, FC1_OUT, FC1_IN, FC1_IN/8);
        int total = NROWS*FC1_OUT;
        k_reduce_bias<<<(total + 255)/256, 256>>>(fc1_b, 0, FC1_OUT, 8);
        int nlif = BB*FC1_OUT;
        k_lif<<<(nlif + 255)/256, 256>>>(0, FC1_OUT);
    }
    // 4) fc2 GEMM + reduce + LIF
    {
        dim3 grid(FC2_OUT/64, NROWS/64, 1);
        k_gemm<<<grid, 256>>>(fc2_w, 1, FC2_OUT, FC1_OUT, FC1_OUT);
        int total = NROWS*FC2_OUT;
        k_reduce_bias<<<(total + 255)/256, 256>>>(fc2_b, 1, FC2_OUT, 1);
        int nlif = BB*FC2_OUT;
        k_lif<<<(nlif + 255)/256, 256>>>(1, FC2_OUT);
    }
    // 5) fc3 + LIF + mean -> out [32,7]
    k_fc3_lif_mean<<<BB, 32>>>(fc3_w, fc3_b, out);
}

// round 2
// speedup vs baseline: 1.2895x; 1.2895x over previous
#include <cuda_runtime.h>
#include <cuda_bf16.h>

// ---------------- problem constants ----------------
#define TT 8
#define BB 32
#define C1 128
#define H1 48
#define P1S 24
#define P2S 12
#define FC1_IN  (128*12*12)   // 18432
#define FC1_OUT 1152
#define FC2_OUT 128
#define FC3_OUT 7
#define NROWS (TT*BB)         // 256

// ---------------- scratch ----------------
__device__ unsigned char g_p1[TT*BB*C1*P1S*P1S];
__device__ float g_p2[TT*BB*C1*P2S*P2S];
__device__ float g_part1[8*NROWS*FC1_OUT];
__device__ float g_a1[NROWS*FC1_OUT];
__device__ float g_l1[NROWS*FC1_OUT];
__device__ float g_part2[8*NROWS*FC2_OUT];
__device__ float g_a2[NROWS*FC2_OUT];
__device__ float g_l2[NROWS*FC2_OUT];

// ---------------- packed f32x2 helpers ----------------
__device__ __forceinline__ unsigned long long ffma2(unsigned long long a,
                                                    unsigned long long b,
                                                    unsigned long long c) {
    unsigned long long d;
    asm("fma.rn.f32x2 %0, %1, %2, %3;" : "=l"(d) : "l"(a), "l"(b), "l"(c));
    return d;
}
__device__ __forceinline__ unsigned long long pk2(float lo, float hi) {
    unsigned long long r;
    asm("mov.b64 %0, {%1, %2};" : "=l"(r) : "f"(lo), "f"(hi));
    return r;
}
__device__ __forceinline__ float2 upk2(unsigned long long v) {
    float2 f;
    asm("mov.b64 {%0, %1}, %2;" : "=f"(f.x), "=f"(f.y) : "l"(v));
    return f;
}

// ============================================================
// Kernel 1: conv1 + BN1 + IF over T + maxpool 2x2
// ============================================================
__global__ void k_conv1_if_pool(const float* __restrict__ x,
                                const float* __restrict__ w1,
                                const float* __restrict__ b1,
                                const float* __restrict__ bg,
                                const float* __restrict__ bbta,
                                const float* __restrict__ bm,
                                const float* __restrict__ bv)
{
    int idx = blockIdx.x * blockDim.x + threadIdx.x;
    if (idx >= BB*C1*P1S*P1S) return;
    int p  = idx % (P1S*P1S);
    int c  = (idx / (P1S*P1S)) % C1;
    int b  = idx / (P1S*P1S*C1);
    int py = p / P1S, px = p % P1S;

    float w[9];
#pragma unroll
    for (int k = 0; k < 9; k++) w[k] = w1[c*9 + k];
    float scale = bg[c] * rsqrtf(bv[c] + 1e-5f);
    float add   = (b1[c] - bm[c]) * scale + bbta[c];

    const float* xb = x + b*H1*H1;
    float h[4];
#pragma unroll
    for (int d = 0; d < 4; d++) {
        int y  = 2*py + (d >> 1);
        int xx = 2*px + (d & 1);
        float s = 0.f;
#pragma unroll
        for (int ky = 0; ky < 3; ky++) {
            int gy = y + ky - 1;
            if (gy < 0 || gy >= H1) continue;
#pragma unroll
            for (int kx = 0; kx < 3; kx++) {
                int gx = xx + kx - 1;
                if (gx < 0 || gx >= H1) continue;
                s += xb[gy*H1 + gx] * w[ky*3 + kx];
            }
        }
        h[d] = s * scale + add;
    }

    float v[4] = {0.f, 0.f, 0.f, 0.f};
#pragma unroll
    for (int t = 0; t < TT; t++) {
        unsigned char any = 0;
#pragma unroll
        for (int d = 0; d < 4; d++) {
            v[d] += h[d];
            if (v[d] >= 1.0f) { any = 1; v[d] = 0.f; }
        }
        g_p1[((t*BB + b)*C1 + c)*(P1S*P1S) + p] = any;
    }
}

// ============================================================
// Kernel 2: conv2 + BN2 + IF over T + maxpool, FFMA2 over t-pairs.
// 256 thr = 32 oc-lanes x 8 quad-slots; each thread: one pooled output,
// 8 timesteps as 4 packed f32x2 accumulators per quad pixel.
// ============================================================
__global__ void __launch_bounds__(256, 2)
k_conv2_if_pool(const float* __restrict__ w2,
                const float* __restrict__ b2,
                const float* __restrict__ bg,
                const float* __restrict__ bbta,
                const float* __restrict__ bm,
                const float* __restrict__ bv)
{
    __shared__ float2 in_s[4*8*6*10];   // [tp][ic(8)][row 6][col 10], pair=(t even,t odd)
    __shared__ float  w_s[72*33];       // [(ic*9+k)*33 + oc]

    int tid  = threadIdx.x;
    int oc_l = tid & 31;
    int slot = tid >> 5;
    int qtx = blockIdx.x % 3;
    int qty = blockIdx.x / 3;
    int b   = blockIdx.z;
    int oc  = blockIdx.y * 32 + oc_l;
    int sx = slot & 3, sy = slot >> 2;

    unsigned long long acc[16];          // [tp][quad d]
#pragma unroll
    for (int i = 0; i < 16; i++) acc[i] = 0ULL;

    int gy0 = qty*4 - 1;
    int gx0 = qtx*8 - 1;

    const unsigned long long* inp = reinterpret_cast<const unsigned long long*>(in_s);

    for (int ch = 0; ch < 16; ch++) {
        int ic0 = ch * 8;
        // ---- stage spikes as (t, t+1) float2 pairs ----
        for (int e = tid; e < 4*8*60; e += 256) {
            int rx = e % 10;
            int tmp = e / 10;
            int ry = tmp % 6; tmp /= 6;
            int ic = tmp % 8;
            int tp = tmp / 8;
            int gy = gy0 + ry, gx = gx0 + rx;
            float v0 = 0.f, v1 = 0.f;
            if ((unsigned)gy < (unsigned)P1S && (unsigned)gx < (unsigned)P1S) {
                int base = ((2*tp*BB + b)*C1 + ic0 + ic)*(P1S*P1S) + gy*P1S + gx;
                v0 = (float)g_p1[base];
                v1 = (float)g_p1[base + BB*C1*(P1S*P1S)];
            }
            in_s[e] = make_float2(v0, v1);
        }
        // ---- stage weights transposed ----
        for (int e = tid; e < 32*72; e += 256) {
            int o = e / 72;
            int r = e % 72;
            w_s[r*33 + o] = w2[((blockIdx.y*32 + o)*C1 + ic0 + r/9)*9 + (r % 9)];
        }
        __syncthreads();

#pragma unroll
        for (int ic = 0; ic < 8; ic++) {
            unsigned long long wp[9];
#pragma unroll
            for (int k = 0; k < 9; k++) {
                float w = w_s[(ic*9 + k)*33 + oc_l];
                wp[k] = pk2(w, w);
            }
#pragma unroll
            for (int tp = 0; tp < 4; tp++) {
                const unsigned long long* base = inp + ((tp*8 + ic)*6 + sy*2)*10 + sx*2;
                unsigned long long pin[4][4];
#pragma unroll
                for (int ry = 0; ry < 4; ry++)
#pragma unroll
                    for (int rx = 0; rx < 4; rx++)
                        pin[ry][rx] = base[ry*10 + rx];
#pragma unroll
                for (int py = 0; py < 2; py++)
#pragma unroll
                    for (int px = 0; px < 2; px++) {
                        unsigned long long s = acc[tp*4 + py*2 + px];
#pragma unroll
                        for (int ky = 0; ky < 3; ky++)
#pragma unroll
                            for (int kx = 0; kx < 3; kx++)
                                s = ffma2(wp[ky*3 + kx], pin[py + ky][px + kx], s);
                        acc[tp*4 + py*2 + px] = s;
                    }
            }
        }
        __syncthreads();
    }

    // BN2 + IF over T + 2x2 max pool
    float scale = bg[oc] * rsqrtf(bv[oc] + 1e-5f);
    float add   = (b2[oc] - bm[oc]) * scale + bbta[oc];
    float v[4] = {0.f, 0.f, 0.f, 0.f};
    int qx = qtx*4 + sx;
    int qy = qty*2 + sy;
#pragma unroll
    for (int tp = 0; tp < 4; tp++) {
        float2 u[4];
#pragma unroll
        for (int d = 0; d < 4; d++) u[d] = upk2(acc[tp*4 + d]);
#pragma unroll
        for (int half = 0; half < 2; half++) {
            int t = 2*tp + half;
            float any = 0.f;
#pragma unroll
            for (int d = 0; d < 4; d++) {
                float c = half ? u[d].y : u[d].x;
                v[d] += c * scale + add;
                if (v[d] >= 1.0f) { any = 1.f; v[d] = 0.f; }
            }
            g_p2[((t*BB + b)*C1 + oc)*(P2S*P2S) + qy*P2S + qx] = any;
        }
    }
}

// ============================================================
// GEMM: C = A * B^T with FFMA2 row-pair packing.
// Tile 128(M) x 64(N) x 16(K). 256 threads, thread tile 8x4.
// Smem stored k-major transposed: AsT[k][row], BsT[k][n].
// Deterministic split-K partials via blockIdx.z.
// ============================================================
__global__ void __launch_bounds__(256)
k_gemm(const float* __restrict__ Bmat, int which, int N, int K, int klen)
{
    __shared__ float AsT[16][130];  // [k][row 0..127]
    __shared__ float BsT[16][66];   // [k][n 0..63]
    const float* A = (which == 0) ? g_p2 : g_l1;
    float* P       = (which == 0) ? g_part1 : g_part2;

    int tid = threadIdx.x;
    int tx = tid & 15, ty = tid >> 4;
    int bm = blockIdx.y, bn = blockIdx.x, sz = blockIdx.z;
    int ks = sz * klen;
    int ke = ks + klen;

    unsigned long long acc[4][4];   // [row-pair ip][n j]; pair = rows (2ip, 2ip+1)
#pragma unroll
    for (int i = 0; i < 4; i++)
#pragma unroll
        for (int j = 0; j < 4; j++) acc[i][j] = 0ULL;

    for (int kk = ks; kk < ke; kk += 16) {
        // stage A tile (128x16) transposed
#pragma unroll
        for (int l = 0; l < 2; l++) {
            int lin = tid + l*256;
            int row = lin >> 2, cg = lin & 3;
            const float4 va = *reinterpret_cast<const float4*>(
                &A[(size_t)(bm*128 + row)*K + kk + cg*4]);
            AsT[cg*4 + 0][row] = va.x;
            AsT[cg*4 + 1][row] = va.y;
            AsT[cg*4 + 2][row] = va.z;
            AsT[cg*4 + 3][row] = va.w;
        }
        // stage B tile (64x16) transposed
        {
            int row = tid >> 2, cg = tid & 3;
            const float4 vb = *reinterpret_cast<const float4*>(
                &Bmat[(size_t)(bn*64 + row)*K + kk + cg*4]);
            BsT[cg*4 + 0][row] = vb.x;
            BsT[cg*4 + 1][row] = vb.y;
            BsT[cg*4 + 2][row] = vb.z;
            BsT[cg*4 + 3][row] = vb.w;
        }
        __syncthreads();

#pragma unroll
        for (int c = 0; c < 16; c++) {
            unsigned long long a2[4];
#pragma unroll
            for (int ip = 0; ip < 4; ip++)
                a2[ip] = *reinterpret_cast<const unsigned long long*>(
                    &AsT[c][ty*8 + ip*2]);
            unsigned long long b2[4];
#pragma unroll
            for (int j = 0; j < 4; j++) {
                float bv = BsT[c][tx*4 + j];
                b2[j] = pk2(bv, bv);
            }
#pragma unroll
            for (int ip = 0; ip < 4; ip++)
#pragma unroll
                for (int j = 0; j < 4; j++)
                    acc[ip][j] = ffma2(a2[ip], b2[j], acc[ip][j]);
        }
        __syncthreads();
    }

#pragma unroll
    for (int ip = 0; ip < 4; ip++)
#pragma unroll
        for (int j = 0; j < 4; j++) {
            float2 u = upk2(acc[ip][j]);
            int row = bm*128 + ty*8 + ip*2;
            int col = bn*64 + tx*4 + j;
            P[(size_t)sz*NROWS*N + (size_t)row*N + col] = u.x;
            P[(size_t)sz*NROWS*N + (size_t)(row+1)*N + col] = u.y;
        }
}

// Deterministic split-K reduction + bias
__global__ void k_reduce_bias(const float* __restrict__ bias, int which, int N, int S)
{
    const float* P = (which == 0) ? g_part1 : g_part2;
    float* C       = (which == 0) ? g_a1 : g_a2;
    int idx = blockIdx.x * blockDim.x + threadIdx.x;
    if (idx >= NROWS*N) return;
    float s = bias[idx % N];
    for (int z = 0; z < S; z++) s += P[(size_t)z*NROWS*N + idx];
    C[idx] = s;
}

// LIF over T (tau=2, vth=1, hard reset)
__global__ void k_lif(int which, int N)
{
    const float* A = (which == 0) ? g_a1 : g_a2;
    float* L       = (which == 0) ? g_l1 : g_l2;
    int idx = blockIdx.x * blockDim.x + threadIdx.x;
    if (idx >= BB*N) return;
    int b = idx / N, o = idx % N;
    float v = 0.f;
#pragma unroll
    for (int t = 0; t < TT; t++) {
        float x = A[(t*BB + b)*N + o];
        v += (x - v) * 0.5f;
        float s = (v >= 1.0f) ? 1.f : 0.f;
        L[(t*BB + b)*N + o] = s;
        if (s != 0.f) v = 0.f;
    }
}

// fc3 + LIF + mean over T
__global__ void k_fc3_lif_mean(const float* __restrict__ w,
                               const float* __restrict__ bias,
                               float* __restrict__ out)
{
    __shared__ float row[FC2_OUT];
    int b = blockIdx.x, tid = threadIdx.x;
    float v = 0.f, acc = 0.f;
#pragma unroll
    for (int t = 0; t < TT; t++) {
        for (int i = tid; i < FC2_OUT; i += 32)
            row[i] = g_l2[(t*BB + b)*FC2_OUT + i];
        __syncthreads();
        if (tid < FC3_OUT) {
            float s = bias[tid];
#pragma unroll 8
            for (int i = 0; i < FC2_OUT; i++) s += row[i] * w[tid*FC2_OUT + i];
            v += (s - v) * 0.5f;
            if (v >= 1.0f) { acc += 1.f; v = 0.f; }
        }
        __syncthreads();
    }
    if (tid < FC3_OUT) out[b*FC3_OUT + tid] = acc * 0.125f;
}

// ============================================================
extern "C" void kernel_launch(void* const* d_in, const int* in_sizes, int n_in,
                              void* d_out, int out_size)
{
    const float* x       = (const float*)d_in[0];
    const float* conv1_w = (const float*)d_in[1];
    const float* conv1_b = (const float*)d_in[2];
    const float* bn1_g   = (const float*)d_in[3];
    const float* bn1_b   = (const float*)d_in[4];
    const float* bn1_m   = (const float*)d_in[5];
    const float* bn1_v   = (const float*)d_in[6];
    const float* conv2_w = (const float*)d_in[7];
    const float* conv2_b = (const float*)d_in[8];
    const float* bn2_g   = (const float*)d_in[9];
    const float* bn2_b   = (const float*)d_in[10];
    const float* bn2_m   = (const float*)d_in[11];
    const float* bn2_v   = (const float*)d_in[12];
    const float* fc1_w   = (const float*)d_in[13];
    const float* fc1_b   = (const float*)d_in[14];
    const float* fc2_w   = (const float*)d_in[15];
    const float* fc2_b   = (const float*)d_in[16];
    const float* fc3_w   = (const float*)d_in[17];
    const float* fc3_b   = (const float*)d_in[18];
    float* out = (float*)d_out;

    {
        int total = BB*C1*P1S*P1S;
        k_conv1_if_pool<<<(total + 255)/256, 256>>>(x, conv1_w, conv1_b,
                                                    bn1_g, bn1_b, bn1_m, bn1_v);
    }
    {
        dim3 grid(18, 4, BB);
        k_conv2_if_pool<<<grid, 256>>>(conv2_w, conv2_b, bn2_g, bn2_b, bn2_m, bn2_v);
    }
    {   // fc1: split-K = 8
        dim3 grid(FC1_OUT/64, NROWS/128, 8);
        k_gemm<<<grid, 256>>>(fc1_w, 0, FC1_OUT, FC1_IN, FC1_IN/8);
        int total = NROWS*FC1_OUT;
        k_reduce_bias<<<(total + 255)/256, 256>>>(fc1_b, 0, FC1_OUT, 8);
        int nlif = BB*FC1_OUT;
        k_lif<<<(nlif + 255)/256, 256>>>(0, FC1_OUT);
    }
    {   // fc2: split-K = 8
        dim3 grid(FC2_OUT/64, NROWS/128, 8);
        k_gemm<<<grid, 256>>>(fc2_w, 1, FC2_OUT, FC1_OUT, FC1_OUT/8);
        int total = NROWS*FC2_OUT;
        k_reduce_bias<<<(total + 255)/256, 256>>>(fc2_b, 1, FC2_OUT, 8);
        int nlif = BB*FC2_OUT;
        k_lif<<<(nlif + 255)/256, 256>>>(1, FC2_OUT);
    }
    k_fc3_lif_mean<<<BB, 32>>>(fc3_w, fc3_b, out);
}

// round 4
// speedup vs baseline: 2.7605x; 2.1407x over previous
#include <cuda_runtime.h>
#include <cuda_bf16.h>
#include <cstdint>

// ---------------- problem constants ----------------
#define TT 8
#define BB 32
#define C1 128
#define H1 48
#define P1S 24
#define P2S 12
#define FC1_IN  (128*12*12)   // 18432
#define FC1_OUT 1152
#define FC2_OUT 128
#define FC3_OUT 7
#define NROWS (TT*BB)         // 256
#define MTOT  (NROWS*P1S*P1S) // 147456 conv2 GEMM rows
#define SZW1  (FC1_OUT*FC1_IN)

// ---------------- scratch (static device memory) ----------------
__device__ __nv_bfloat16 g_p1b[(size_t)MTOT*128];        // spikes after pool1, NHWC bf16
__device__ float         g_c2[(size_t)MTOT*128];          // conv2 pre-activations
__device__ __nv_bfloat16 g_s2[(size_t)NROWS*144*128];     // spikes after pool2, HWC bf16
__device__ __nv_bfloat16 g_w2s[3*9*128*128];              // conv2 w 3-split [s][koff][oc][ic]
__device__ __nv_bfloat16 g_w1s[3ULL*SZW1];                // fc1 w 3-split, K' = p*128+c
__device__ float g_part1[16*NROWS*FC1_OUT];
__device__ float g_a1[NROWS*FC1_OUT];
__device__ float g_l1[NROWS*FC1_OUT];
__device__ float g_part2[8*NROWS*FC2_OUT];
__device__ float g_a2[NROWS*FC2_OUT];
__device__ float g_l2[NROWS*FC2_OUT];

// ---------------- packed f32x2 helpers ----------------
__device__ __forceinline__ unsigned long long ffma2(unsigned long long a,
                                                    unsigned long long b,
                                                    unsigned long long c) {
    unsigned long long d;
    asm("fma.rn.f32x2 %0, %1, %2, %3;" : "=l"(d) : "l"(a), "l"(b), "l"(c));
    return d;
}
__device__ __forceinline__ unsigned long long pk2(float lo, float hi) {
    unsigned long long r;
    asm("mov.b64 %0, {%1, %2};" : "=l"(r) : "f"(lo), "f"(hi));
    return r;
}
__device__ __forceinline__ float2 upk2(unsigned long long v) {
    float2 f;
    asm("mov.b64 {%0, %1}, %2;" : "=f"(f.x), "=f"(f.y) : "l"(v));
    return f;
}

// ---------------- mma.sync bf16 helpers (baseline sm_80+ ISA) ----------------
__device__ __forceinline__ void hmma(float* d, const uint32_t* a, uint32_t b0, uint32_t b1) {
    asm volatile(
        "mma.sync.aligned.m16n8k16.row.col.f32.bf16.bf16.f32 "
        "{%0,%1,%2,%3}, {%4,%5,%6,%7}, {%8,%9}, {%0,%1,%2,%3};"
        : "+f"(d[0]), "+f"(d[1]), "+f"(d[2]), "+f"(d[3])
        : "r"(a[0]), "r"(a[1]), "r"(a[2]), "r"(a[3]), "r"(b0), "r"(b1));
}
__device__ __forceinline__ uint32_t swz(uint32_t off) { return off ^ ((off >> 3) & 0x70); }

// ============================================================
// Prep: split conv2 weights into 3 bf16 terms, [s][koff][oc][ic]
// ============================================================
__global__ void k_prep_w2(const float* __restrict__ w2)
{
    int idx = blockIdx.x * blockDim.x + threadIdx.x;
    if (idx >= 128*128*9) return;
    int oc = idx / 1152;
    int r  = idx % 1152;
    int ic = r / 9, k = r % 9;
    float w = w2[idx];
    __nv_bfloat16 h = __float2bfloat16(w);
    float r1 = w - __bfloat162float(h);
    __nv_bfloat16 m = __float2bfloat16(r1);
    float r2 = r1 - __bfloat162float(m);
    __nv_bfloat16 l = __float2bfloat16(r2);
    size_t d = ((size_t)k*128 + oc)*128 + ic;
    g_w2s[d] = h;
    g_w2s[(size_t)9*128*128 + d] = m;
    g_w2s[(size_t)18*128*128 + d] = l;
}

// ============================================================
// Prep: split + transpose fc1 weights: K' = (py*12+px)*128 + c
// ============================================================
__global__ void k_prep_w1(const float* __restrict__ w1)
{
    __shared__ float tile[2304];           // [c 16][p 144]
    int n = blockIdx.x, c0 = blockIdx.y * 16;
    int tid = threadIdx.x;
    for (int i = tid; i < 2304; i += 256) {
        int c = i / 144, p = i % 144;
        tile[i] = w1[(size_t)n*FC1_IN + (c0 + c)*144 + p];
    }
    __syncthreads();
    for (int i = tid; i < 2304; i += 256) {
        int p = i / 16, cl = i % 16;
        float w = tile[cl*144 + p];
        __nv_bfloat16 h = __float2bfloat16(w);
        float r1 = w - __bfloat162float(h);
        __nv_bfloat16 m = __float2bfloat16(r1);
        float r2 = r1 - __bfloat162float(m);
        __nv_bfloat16 l = __float2bfloat16(r2);
        size_t d = (size_t)n*FC1_IN + p*128 + c0 + cl;
        g_w1s[d] = h;
        g_w1s[(size_t)SZW1 + d] = m;
        g_w1s[(size_t)2*SZW1 + d] = l;
    }
}

// ============================================================
// conv1 + BN1 + IF over T + maxpool -> g_p1b NHWC bf16 spikes
// ============================================================
__global__ void k_conv1_if_pool(const float* __restrict__ x,
                                const float* __restrict__ w1,
                                const float* __restrict__ b1,
                                const float* __restrict__ bg,
                                const float* __restrict__ bbta,
                                const float* __restrict__ bm,
                                const float* __restrict__ bv)
{
    int idx = blockIdx.x * blockDim.x + threadIdx.x;
    if (idx >= BB*P1S*P1S*128) return;
    int c   = idx & 127;
    int pos = idx >> 7;
    int b   = pos / (P1S*P1S);
    int p   = pos % (P1S*P1S);
    int py = p / P1S, px = p % P1S;

    float w[9];
#pragma unroll
    for (int k = 0; k < 9; k++) w[k] = w1[c*9 + k];
    float scale = bg[c] * rsqrtf(bv[c] + 1e-5f);
    float add   = (b1[c] - bm[c]) * scale + bbta[c];

    const float* xb = x + b*H1*H1;
    float h[4];
#pragma unroll
    for (int d = 0; d < 4; d++) {
        int y  = 2*py + (d >> 1);
        int xx = 2*px + (d & 1);
        float s = 0.f;
#pragma unroll
        for (int ky = 0; ky < 3; ky++) {
            int gy = y + ky - 1;
            if (gy < 0 || gy >= H1) continue;
#pragma unroll
            for (int kx = 0; kx < 3; kx++) {
                int gx = xx + kx - 1;
                if (gx < 0 || gx >= H1) continue;
                s += xb[gy*H1 + gx] * w[ky*3 + kx];
            }
        }
        h[d] = s * scale + add;
    }

    float v[4] = {0.f, 0.f, 0.f, 0.f};
#pragma unroll
    for (int t = 0; t < TT; t++) {
        float any = 0.f;
#pragma unroll
        for (int d = 0; d < 4; d++) {
            v[d] += h[d];
            if (v[d] >= 1.0f) { any = 1.f; v[d] = 0.f; }
        }
        g_p1b[((size_t)(t*BB + b)*576 + p)*128 + c] = __float2bfloat16(any);
    }
}

// ============================================================
// conv2 as implicit-im2col HMMA bf16 GEMM, exact 3-split weights.
// Block: 128 rows x 128 oc, 8 warps (4M x 2N), warp tile 32x64.
// 18 stages of (koff x ic-chunk-64); 3 splits accumulate together.
// Smem: A 128x64 @0 (16KB), B 3x128x64 @16KB (48KB).
// ============================================================
__global__ void __launch_bounds__(256, 2) k_conv2_mma()
{
    extern __shared__ unsigned char dsm[];
    uint32_t sb0;
    asm("{ .reg .u64 t; cvta.to.shared.u64 t, %1; cvt.u32.u64 %0, t; }" : "=r"(sb0) : "l"(dsm));
    uint32_t sb = (sb0 + 1023) & ~1023u;
    unsigned char* sm = dsm + (sb - sb0);

    int tid = threadIdx.x, wid = tid >> 5, lane = tid & 31;
    int wm = wid & 3, wn = wid >> 2;
    int mbase = blockIdx.x * 128;
    int gid = lane >> 2, qid = lane & 3;

    float acc[2][8][4];
#pragma unroll
    for (int i = 0; i < 2; i++)
#pragma unroll
        for (int j = 0; j < 8; j++)
#pragma unroll
            for (int k = 0; k < 4; k++) acc[i][j][k] = 0.f;

    for (int koff = 0; koff < 9; koff++) {
        int ky = koff/3 - 1, kx = koff%3 - 1;
        for (int icc = 0; icc < 2; icc++) {
            // ---- stage A: 128 rows x 64 ic (im2col, swizzled) ----
#pragma unroll
            for (int l = 0; l < 4; l++) {
                int e = tid + l*256;
                int r = e >> 3, ln = e & 7;
                int m = mbase + r;
                int img = m / 576;
                int pix = m - img*576;
                int y = pix / 24, x = pix - y*24;
                int gy = y + ky, gx = x + kx;
                uint4 v = make_uint4(0,0,0,0);
                if ((unsigned)gy < 24u && (unsigned)gx < 24u)
                    v = ((const uint4*)(g_p1b +
                        ((size_t)(img*576 + gy*24 + gx)*128 + icc*64)))[ln];
                *(uint4*)(sm + swz((uint32_t)(r*128 + ln*16))) = v;
            }
            // ---- stage B: 3 splits x 128 oc x 64 ic ----
#pragma unroll
            for (int l = 0; l < 12; l++) {
                int e = tid + l*256;
                int s = e >> 10, r = (e >> 3) & 127, ln = e & 7;
                uint4 v = ((const uint4*)(g_w2s +
                    ((size_t)((s*9 + koff)*128 + r)*128 + icc*64)))[ln];
                *(uint4*)(sm + 16384 + s*16384 + swz((uint32_t)(r*128 + ln*16))) = v;
            }
            __syncthreads();

#pragma unroll
            for (int kk = 0; kk < 4; kk++) {
                int kb = kk*32 + qid*4;
                uint32_t a[2][4];
#pragma unroll
                for (int mi = 0; mi < 2; mi++) {
                    int r0 = wm*32 + mi*16 + gid;
                    a[mi][0] = *(const uint32_t*)(sm + swz((uint32_t)(r0*128 + kb)));
                    a[mi][1] = *(const uint32_t*)(sm + swz((uint32_t)((r0+8)*128 + kb)));
                    a[mi][2] = *(const uint32_t*)(sm + swz((uint32_t)(r0*128 + kb + 16)));
                    a[mi][3] = *(const uint32_t*)(sm + swz((uint32_t)((r0+8)*128 + kb + 16)));
                }
#pragma unroll
                for (int s = 0; s < 3; s++) {
                    const unsigned char* bs = sm + 16384 + s*16384;
#pragma unroll
                    for (int ni = 0; ni < 8; ni++) {
                        int n0 = wn*64 + ni*8 + gid;
                        uint32_t b0 = *(const uint32_t*)(bs + swz((uint32_t)(n0*128 + kb)));
                        uint32_t b1 = *(const uint32_t*)(bs + swz((uint32_t)(n0*128 + kb + 16)));
                        hmma(acc[0][ni], a[0], b0, b1);
                        hmma(acc[1][ni], a[1], b0, b1);
                    }
                }
            }
            __syncthreads();
        }
    }

    // ---- epilogue -> g_c2 fp32 ----
#pragma unroll
    for (int mi = 0; mi < 2; mi++) {
        int m = mbase + wm*32 + mi*16 + gid;
#pragma unroll
        for (int ni = 0; ni < 8; ni++) {
            int n = wn*64 + ni*8 + qid*2;
            *(float2*)(g_c2 + (size_t)m*128 + n)     = make_float2(acc[mi][ni][0], acc[mi][ni][1]);
            *(float2*)(g_c2 + (size_t)(m+8)*128 + n) = make_float2(acc[mi][ni][2], acc[mi][ni][3]);
        }
    }
}

// ============================================================
// BN2 + IF over T + maxpool on g_c2 -> g_s2 (HWC bf16 spikes)
// ============================================================
__global__ void k_if2_pool(const float* __restrict__ b2,
                           const float* __restrict__ bg,
                           const float* __restrict__ bbta,
                           const float* __restrict__ bm,
                           const float* __restrict__ bv)
{
    int pos = blockIdx.x;
    int b = pos / 144, pp = pos % 144;
    int py = pp / 12, px = pp % 12;
    int oc = threadIdx.x;

    float scale = bg[oc] * rsqrtf(bv[oc] + 1e-5f);
    float add   = (b2[oc] - bm[oc]) * scale + bbta[oc];

    float v[4] = {0.f, 0.f, 0.f, 0.f};
#pragma unroll
    for (int t = 0; t < TT; t++) {
        float any = 0.f;
#pragma unroll
        for (int d = 0; d < 4; d++) {
            int m = (t*BB + b)*576 + (2*py + (d>>1))*24 + (2*px + (d&1));
            float xx = g_c2[(size_t)m*128 + oc] * scale + add;
            v[d] += xx;
            if (v[d] >= 1.0f) { any = 1.f; v[d] = 0.f; }
        }
        g_s2[((size_t)(t*BB + b)*144 + pp)*128 + oc] = __float2bfloat16(any);
    }
}

// ============================================================
// fc1 as HMMA bf16 GEMM, split-K=16, exact 3-split weights.
// grid (9 n-tiles, 2 m-tiles, 16 slices). Block 128x128, same engine.
// ============================================================
__global__ void __launch_bounds__(256, 2) k_fc1_mma()
{
    extern __shared__ unsigned char dsm[];
    uint32_t sb0;
    asm("{ .reg .u64 t; cvta.to.shared.u64 t, %1; cvt.u32.u64 %0, t; }" : "=r"(sb0) : "l"(dsm));
    uint32_t sb = (sb0 + 1023) & ~1023u;
    unsigned char* sm = dsm + (sb - sb0);

    int tid = threadIdx.x, wid = tid >> 5, lane = tid & 31;
    int wm = wid & 3, wn = wid >> 2;
    int gid = lane >> 2, qid = lane & 3;

    int nbase = blockIdx.x * 128;
    int mbase = blockIdx.y * 128;
    int slice = blockIdx.z;
    int kbase = slice * 1152;

    float acc[2][8][4];
#pragma unroll
    for (int i = 0; i < 2; i++)
#pragma unroll
        for (int j = 0; j < 8; j++)
#pragma unroll
            for (int k = 0; k < 4; k++) acc[i][j][k] = 0.f;

    for (int c = 0; c < 18; c++) {
        int k0 = kbase + c*64;
        // ---- stage A: 128 rows x 64 k ----
#pragma unroll
        for (int l = 0; l < 4; l++) {
            int e = tid + l*256;
            int r = e >> 3, ln = e & 7;
            uint4 v = ((const uint4*)(g_s2 + (size_t)(mbase + r)*FC1_IN + k0))[ln];
            *(uint4*)(sm + swz((uint32_t)(r*128 + ln*16))) = v;
        }
        // ---- stage B: 3 splits x 128 n x 64 k ----
#pragma unroll
        for (int l = 0; l < 12; l++) {
            int e = tid + l*256;
            int s = e >> 10, r = (e >> 3) & 127, ln = e & 7;
            uint4 v = ((const uint4*)(g_w1s +
                ((size_t)s*SZW1 + (size_t)(nbase + r)*FC1_IN + k0)))[ln];
            *(uint4*)(sm + 16384 + s*16384 + swz((uint32_t)(r*128 + ln*16))) = v;
        }
        __syncthreads();

#pragma unroll
        for (int kk = 0; kk < 4; kk++) {
            int kb = kk*32 + qid*4;
            uint32_t a[2][4];
#pragma unroll
            for (int mi = 0; mi < 2; mi++) {
                int r0 = wm*32 + mi*16 + gid;
                a[mi][0] = *(const uint32_t*)(sm + swz((uint32_t)(r0*128 + kb)));
                a[mi][1] = *(const uint32_t*)(sm + swz((uint32_t)((r0+8)*128 + kb)));
                a[mi][2] = *(const uint32_t*)(sm + swz((uint32_t)(r0*128 + kb + 16)));
                a[mi][3] = *(const uint32_t*)(sm + swz((uint32_t)((r0+8)*128 + kb + 16)));
            }
#pragma unroll
            for (int s = 0; s < 3; s++) {
                const unsigned char* bs = sm + 16384 + s*16384;
#pragma unroll
                for (int ni = 0; ni < 8; ni++) {
                    int n0 = wn*64 + ni*8 + gid;
                    uint32_t b0 = *(const uint32_t*)(bs + swz((uint32_t)(n0*128 + kb)));
                    uint32_t b1 = *(const uint32_t*)(bs + swz((uint32_t)(n0*128 + kb + 16)));
                    hmma(acc[0][ni], a[0], b0, b1);
                    hmma(acc[1][ni], a[1], b0, b1);
                }
            }
        }
        __syncthreads();
    }

    // ---- epilogue -> g_part1[slice] ----
#pragma unroll
    for (int mi = 0; mi < 2; mi++) {
        int m = mbase + wm*32 + mi*16 + gid;
#pragma unroll
        for (int ni = 0; ni < 8; ni++) {
            int n = nbase + wn*64 + ni*8 + qid*2;
            float* dst = g_part1 + ((size_t)slice*NROWS + m)*FC1_OUT + n;
            *(float2*)dst = make_float2(acc[mi][ni][0], acc[mi][ni][1]);
            *(float2*)(dst + 8*FC1_OUT) = make_float2(acc[mi][ni][2], acc[mi][ni][3]);
        }
    }
}

// ============================================================
// fc2 scalar FFMA2 GEMM: C = A*B^T, A=g_l1
// ============================================================
__global__ void __launch_bounds__(256)
k_gemm2(const float* __restrict__ Bmat, int N, int K, int klen)
{
    __shared__ float AsT[16][130];
    __shared__ float BsT[16][66];
    const float* A = g_l1;
    float* P = g_part2;

    int tid = threadIdx.x;
    int tx = tid & 15, ty = tid >> 4;
    int bm = blockIdx.y, bn = blockIdx.x, sz = blockIdx.z;
    int ks = sz * klen, ke = ks + klen;

    unsigned long long acc[4][4];
#pragma unroll
    for (int i = 0; i < 4; i++)
#pragma unroll
        for (int j = 0; j < 4; j++) acc[i][j] = 0ULL;

    for (int kk = ks; kk < ke; kk += 16) {
#pragma unroll
        for (int l = 0; l < 2; l++) {
            int lin = tid + l*256;
            int row = lin >> 2, cg = lin & 3;
            const float4 va = *reinterpret_cast<const float4*>(
                &A[(size_t)(bm*128 + row)*K + kk + cg*4]);
            AsT[cg*4 + 0][row] = va.x; AsT[cg*4 + 1][row] = va.y;
            AsT[cg*4 + 2][row] = va.z; AsT[cg*4 + 3][row] = va.w;
        }
        {
            int row = tid >> 2, cg = tid & 3;
            const float4 vb = *reinterpret_cast<const float4*>(
                &Bmat[(size_t)(bn*64 + row)*K + kk + cg*4]);
            BsT[cg*4 + 0][row] = vb.x; BsT[cg*4 + 1][row] = vb.y;
            BsT[cg*4 + 2][row] = vb.z; BsT[cg*4 + 3][row] = vb.w;
        }
        __syncthreads();
#pragma unroll
        for (int c = 0; c < 16; c++) {
            unsigned long long a2[4];
#pragma unroll
            for (int ip = 0; ip < 4; ip++)
                a2[ip] = *reinterpret_cast<const unsigned long long*>(&AsT[c][ty*8 + ip*2]);
            unsigned long long b2[4];
#pragma unroll
            for (int j = 0; j < 4; j++) {
                float bv = BsT[c][tx*4 + j];
                b2[j] = pk2(bv, bv);
            }
#pragma unroll
            for (int ip = 0; ip < 4; ip++)
#pragma unroll
                for (int j = 0; j < 4; j++)
                    acc[ip][j] = ffma2(a2[ip], b2[j], acc[ip][j]);
        }
        __syncthreads();
    }
#pragma unroll
    for (int ip = 0; ip < 4; ip++)
#pragma unroll
        for (int j = 0; j < 4; j++) {
            float2 u = upk2(acc[ip][j]);
            int row = bm*128 + ty*8 + ip*2;
            int col = bn*64 + tx*4 + j;
            P[(size_t)sz*NROWS*N + (size_t)row*N + col] = u.x;
            P[(size_t)sz*NROWS*N + (size_t)(row+1)*N + col] = u.y;
        }
}

// Deterministic split-K reduction + bias
__global__ void k_reduce_bias(const float* __restrict__ bias, int which, int N, int S)
{
    const float* P = (which == 0) ? g_part1 : g_part2;
    float* C       = (which == 0) ? g_a1 : g_a2;
    int idx = blockIdx.x * blockDim.x + threadIdx.x;
    if (idx >= NROWS*N) return;
    float s = bias[idx % N];
    for (int z = 0; z < S; z++) s += P[(size_t)z*NROWS*N + idx];
    C[idx] = s;
}

// LIF over T
__global__ void k_lif(int which, int N)
{
    const float* A = (which == 0) ? g_a1 : g_a2;
    float* L       = (which == 0) ? g_l1 : g_l2;
    int idx = blockIdx.x * blockDim.x + threadIdx.x;
    if (idx >= BB*N) return;
    int b = idx / N, o = idx % N;
    float v = 0.f;
#pragma unroll
    for (int t = 0; t < TT; t++) {
        float x = A[(size_t)(t*BB + b)*N + o];
        v += (x - v) * 0.5f;
        float s = (v >= 1.0f) ? 1.f : 0.f;
        L[(size_t)(t*BB + b)*N + o] = s;
        if (s != 0.f) v = 0.f;
    }
}

// fc3 + LIF + mean over T
__global__ void k_fc3_lif_mean(const float* __restrict__ w,
                               const float* __restrict__ bias,
                               float* __restrict__ out)
{
    __shared__ float row[FC2_OUT];
    int b = blockIdx.x, tid = threadIdx.x;
    float v = 0.f, acc = 0.f;
#pragma unroll
    for (int t = 0; t < TT; t++) {
        for (int i = tid; i < FC2_OUT; i += 32)
            row[i] = g_l2[(size_t)(t*BB + b)*FC2_OUT + i];
        __syncthreads();
        if (tid < FC3_OUT) {
            float s = bias[tid];
#pragma unroll 8
            for (int i = 0; i < FC2_OUT; i++) s += row[i] * w[tid*FC2_OUT + i];
            v += (s - v) * 0.5f;
            if (v >= 1.0f) { acc += 1.f; v = 0.f; }
        }
        __syncthreads();
    }
    if (tid < FC3_OUT) out[b*FC3_OUT + tid] = acc * 0.125f;
}

// ============================================================
extern "C" void kernel_launch(void* const* d_in, const int* in_sizes, int n_in,
                              void* d_out, int out_size)
{
    const float* x       = (const float*)d_in[0];
    const float* conv1_w = (const float*)d_in[1];
    const float* conv1_b = (const float*)d_in[2];
    const float* bn1_g   = (const float*)d_in[3];
    const float* bn1_b   = (const float*)d_in[4];
    const float* bn1_m   = (const float*)d_in[5];
    const float* bn1_v   = (const float*)d_in[6];
    const float* conv2_w = (const float*)d_in[7];
    const float* conv2_b = (const float*)d_in[8];
    const float* bn2_g   = (const float*)d_in[9];
    const float* bn2_b   = (const float*)d_in[10];
    const float* bn2_m   = (const float*)d_in[11];
    const float* bn2_v   = (const float*)d_in[12];
    const float* fc1_w   = (const float*)d_in[13];
    const float* fc1_b   = (const float*)d_in[14];
    const float* fc2_w   = (const float*)d_in[15];
    const float* fc2_b   = (const float*)d_in[16];
    const float* fc3_w   = (const float*)d_in[17];
    const float* fc3_b   = (const float*)d_in[18];
    float* out = (float*)d_out;

    const int DSM = 66560;  // 64KB tiles + 1KB alignment slack
    cudaFuncSetAttribute(k_conv2_mma, cudaFuncAttributeMaxDynamicSharedMemorySize, DSM);
    cudaFuncSetAttribute(k_fc1_mma,  cudaFuncAttributeMaxDynamicSharedMemorySize, DSM);

    // 0) weight prep
    k_prep_w2<<<(128*128*9 + 255)/256, 256>>>(conv2_w);
    {
        dim3 g(FC1_OUT, 8);
        k_prep_w1<<<g, 256>>>(fc1_w);
    }
    // 1) conv1 + BN1 + IF + pool
    {
        int total = BB*P1S*P1S*128;
        k_conv1_if_pool<<<(total + 255)/256, 256>>>(x, conv1_w, conv1_b,
                                                    bn1_g, bn1_b, bn1_m, bn1_v);
    }
    // 2) conv2 via HMMA
    k_conv2_mma<<<MTOT/128, 256, DSM>>>();
    // 3) BN2 + IF + pool
    k_if2_pool<<<BB*144, 128>>>(conv2_b, bn2_g, bn2_b, bn2_m, bn2_v);
    // 4) fc1 via HMMA (split-K=16) + reduce + LIF
    {
        dim3 g(FC1_OUT/128, 2, 16);
        k_fc1_mma<<<g, 256, DSM>>>();
        int total = NROWS*FC1_OUT;
        k_reduce_bias<<<(total + 255)/256, 256>>>(fc1_b, 0, FC1_OUT, 16);
        int nlif = BB*FC1_OUT;
        k_lif<<<(nlif + 255)/256, 256>>>(0, FC1_OUT);
    }
    // 5) fc2 FFMA2 GEMM (split-K=8) + reduce + LIF
    {
        dim3 g(FC2_OUT/64, NROWS/128, 8);
        k_gemm2<<<g, 256>>>(fc2_w, FC2_OUT, FC1_OUT, FC1_OUT/8);
        int total = NROWS*FC2_OUT;
        k_reduce_bias<<<(total + 255)/256, 256>>>(fc2_b, 1, FC2_OUT, 8);
        int nlif = BB*FC2_OUT;
        k_lif<<<(nlif + 255)/256, 256>>>(1, FC2_OUT);
    }
    // 6) fc3 + LIF + mean
    k_fc3_lif_mean<<<BB, 32>>>(fc3_w, fc3_b, out);
}

// round 5
// speedup vs baseline: 3.4706x; 1.2572x over previous
#include <cuda_runtime.h>
#include <cuda_bf16.h>
#include <cstdint>

// ---------------- problem constants ----------------
#define TT 8
#define BB 32
#define C1 128
#define H1 48
#define P1S 24
#define P2S 12
#define FC1_IN  (128*12*12)   // 18432
#define FC1_OUT 1152
#define FC2_OUT 128
#define FC3_OUT 7
#define NROWS (TT*BB)         // 256
#define MTOT  (NROWS*P1S*P1S) // 147456
#define SZW1  (FC1_OUT*FC1_IN)

// ---------------- scratch ----------------
__device__ __nv_bfloat16 g_p1b[(size_t)MTOT*128];
__device__ float         g_c2[(size_t)MTOT*128];
__device__ __nv_bfloat16 g_s2[(size_t)NROWS*144*128];
__device__ __nv_bfloat16 g_w2s[3*9*128*128];
__device__ __nv_bfloat16 g_w1s[3ULL*SZW1];
__device__ float g_part1[16*NROWS*FC1_OUT];
__device__ float g_a1[NROWS*FC1_OUT];
__device__ float g_l1[NROWS*FC1_OUT];
__device__ float g_part2[8*NROWS*FC2_OUT];
__device__ float g_a2[NROWS*FC2_OUT];
__device__ float g_l2[NROWS*FC2_OUT];

// ---------------- packed f32x2 helpers ----------------
__device__ __forceinline__ unsigned long long ffma2(unsigned long long a,
                                                    unsigned long long b,
                                                    unsigned long long c) {
    unsigned long long d;
    asm("fma.rn.f32x2 %0, %1, %2, %3;" : "=l"(d) : "l"(a), "l"(b), "l"(c));
    return d;
}
__device__ __forceinline__ unsigned long long pk2(float lo, float hi) {
    unsigned long long r;
    asm("mov.b64 %0, {%1, %2};" : "=l"(r) : "f"(lo), "f"(hi));
    return r;
}
__device__ __forceinline__ float2 upk2(unsigned long long v) {
    float2 f;
    asm("mov.b64 {%0, %1}, %2;" : "=f"(f.x), "=f"(f.y) : "l"(v));
    return f;
}

// ---------------- mma / ldmatrix / cp.async helpers ----------------
__device__ __forceinline__ void hmma(float* d, const uint32_t* a, uint32_t b0, uint32_t b1) {
    asm volatile(
        "mma.sync.aligned.m16n8k16.row.col.f32.bf16.bf16.f32 "
        "{%0,%1,%2,%3}, {%4,%5,%6,%7}, {%8,%9}, {%0,%1,%2,%3};"
        : "+f"(d[0]), "+f"(d[1]), "+f"(d[2]), "+f"(d[3])
        : "r"(a[0]), "r"(a[1]), "r"(a[2]), "r"(a[3]), "r"(b0), "r"(b1));
}
__device__ __forceinline__ void ldsm4(uint32_t& r0, uint32_t& r1, uint32_t& r2, uint32_t& r3,
                                      uint32_t addr) {
    asm volatile("ldmatrix.sync.aligned.m8n8.x4.shared.b16 {%0,%1,%2,%3}, [%4];"
                 : "=r"(r0), "=r"(r1), "=r"(r2), "=r"(r3) : "r"(addr));
}
__device__ __forceinline__ void cpa16(uint32_t dst, const void* src, int srcsize) {
    asm volatile("cp.async.cg.shared.global [%0], [%1], 16, %2;"
                 :: "r"(dst), "l"(src), "r"(srcsize));
}
#define CP_COMMIT() asm volatile("cp.async.commit_group;" ::: "memory")
#define CP_WAIT0()  asm volatile("cp.async.wait_group 0;" ::: "memory")

__device__ __forceinline__ uint32_t swz(uint32_t off) { return off ^ ((off >> 3) & 0x70); }
__device__ __forceinline__ uint32_t smaddr(const void* p) {
    uint32_t a;
    asm("{ .reg .u64 t; cvta.to.shared.u64 t, %1; cvt.u32.u64 %0, t; }" : "=r"(a) : "l"(p));
    return a;
}

// ============================================================
// Prep kernels (3-way exact bf16 weight split)
// ============================================================
__global__ void k_prep_w2(const float* __restrict__ w2)
{
    int idx = blockIdx.x * blockDim.x + threadIdx.x;
    if (idx >= 128*128*9) return;
    int oc = idx / 1152;
    int r  = idx % 1152;
    int ic = r / 9, k = r % 9;
    float w = w2[idx];
    __nv_bfloat16 h = __float2bfloat16(w);
    float r1 = w - __bfloat162float(h);
    __nv_bfloat16 m = __float2bfloat16(r1);
    float r2 = r1 - __bfloat162float(m);
    __nv_bfloat16 l = __float2bfloat16(r2);
    size_t d = ((size_t)k*128 + oc)*128 + ic;
    g_w2s[d] = h;
    g_w2s[(size_t)9*128*128 + d] = m;
    g_w2s[(size_t)18*128*128 + d] = l;
}

__global__ void k_prep_w1(const float* __restrict__ w1)
{
    __shared__ float tile[2304];
    int n = blockIdx.x, c0 = blockIdx.y * 16;
    int tid = threadIdx.x;
    for (int i = tid; i < 2304; i += 256) {
        int c = i / 144, p = i % 144;
        tile[i] = w1[(size_t)n*FC1_IN + (c0 + c)*144 + p];
    }
    __syncthreads();
    for (int i = tid; i < 2304; i += 256) {
        int p = i / 16, cl = i % 16;
        float w = tile[cl*144 + p];
        __nv_bfloat16 h = __float2bfloat16(w);
        float r1 = w - __bfloat162float(h);
        __nv_bfloat16 m = __float2bfloat16(r1);
        float r2 = r1 - __bfloat162float(m);
        __nv_bfloat16 l = __float2bfloat16(r2);
        size_t d = (size_t)n*FC1_IN + p*128 + c0 + cl;
        g_w1s[d] = h;
        g_w1s[(size_t)SZW1 + d] = m;
        g_w1s[(size_t)2*SZW1 + d] = l;
    }
}

// ============================================================
// conv1 + BN1 + IF + pool -> g_p1b (NHWC bf16 spikes)
// ============================================================
__global__ void k_conv1_if_pool(const float* __restrict__ x,
                                const float* __restrict__ w1,
                                const float* __restrict__ b1,
                                const float* __restrict__ bg,
                                const float* __restrict__ bbta,
                                const float* __restrict__ bm,
                                const float* __restrict__ bv)
{
    int idx = blockIdx.x * blockDim.x + threadIdx.x;
    if (idx >= BB*P1S*P1S*128) return;
    int c   = idx & 127;
    int pos = idx >> 7;
    int b   = pos / (P1S*P1S);
    int p   = pos % (P1S*P1S);
    int py = p / P1S, px = p % P1S;

    float w[9];
#pragma unroll
    for (int k = 0; k < 9; k++) w[k] = w1[c*9 + k];
    float scale = bg[c] * rsqrtf(bv[c] + 1e-5f);
    float add   = (b1[c] - bm[c]) * scale + bbta[c];

    const float* xb = x + b*H1*H1;
    float h[4];
#pragma unroll
    for (int d = 0; d < 4; d++) {
        int y  = 2*py + (d >> 1);
        int xx = 2*px + (d & 1);
        float s = 0.f;
#pragma unroll
        for (int ky = 0; ky < 3; ky++) {
            int gy = y + ky - 1;
            if (gy < 0 || gy >= H1) continue;
#pragma unroll
            for (int kx = 0; kx < 3; kx++) {
                int gx = xx + kx - 1;
                if (gx < 0 || gx >= H1) continue;
                s += xb[gy*H1 + gx] * w[ky*3 + kx];
            }
        }
        h[d] = s * scale + add;
    }

    float v[4] = {0.f, 0.f, 0.f, 0.f};
#pragma unroll
    for (int t = 0; t < TT; t++) {
        float any = 0.f;
#pragma unroll
        for (int d = 0; d < 4; d++) {
            v[d] += h[d];
            if (v[d] >= 1.0f) { any = 1.f; v[d] = 0.f; }
        }
        g_p1b[((size_t)(t*BB + b)*576 + p)*128 + c] = __float2bfloat16(any);
    }
}

// ============================================================
// conv2 HMMA GEMM with ldmatrix fragments + cp.async staging.
// Block 128 M x 128 N, 8 warps (4M x 2N), warp tile 32x64.
// ============================================================
__global__ void __launch_bounds__(256, 2) k_conv2_mma()
{
    extern __shared__ unsigned char dsm[];
    uint32_t sb0 = smaddr(dsm);
    uint32_t sb  = (sb0 + 1023) & ~1023u;
    unsigned char* sm = dsm + (sb - sb0);

    int tid = threadIdx.x, wid = tid >> 5, lane = tid & 31;
    int wm = wid & 3, wn = wid >> 2;
    int mbase = blockIdx.x * 128;

    // per-thread ldmatrix address components
    // A: lanes 0-15 rows +0..15 (k-lo), lanes 16-31 same rows (k-hi)
    int a_r[2];
    uint32_t a_base[2], a_xor[2];
#pragma unroll
    for (int mi = 0; mi < 2; mi++) {
        a_r[mi] = wm*32 + mi*16 + (lane & 15);
        a_base[mi] = sb + (uint32_t)(a_r[mi]*128);
        a_xor[mi] = (uint32_t)((a_r[mi] & 7) << 4);
    }
    uint32_t a_kbsel = (uint32_t)((lane >> 4) * 16);
    // B: mat quadrants (n-half x k-half)
    int b_rl = ((lane >> 4) & 1)*8 + (lane & 7);
    uint32_t b_kbsel = (uint32_t)(((lane >> 3) & 1) * 16);

    float acc[2][8][4];
#pragma unroll
    for (int i = 0; i < 2; i++)
#pragma unroll
        for (int j = 0; j < 8; j++)
#pragma unroll
            for (int k = 0; k < 4; k++) acc[i][j][k] = 0.f;

    for (int koff = 0; koff < 9; koff++) {
        int ky = koff/3 - 1, kx = koff%3 - 1;
        for (int icc = 0; icc < 2; icc++) {
            // ---- stage A via cp.async (zero-fill halo) ----
#pragma unroll
            for (int l = 0; l < 4; l++) {
                int e = tid + l*256;
                int r = e >> 3, ln = e & 7;
                int m = mbase + r;
                int img = m / 576;
                int pix = m - img*576;
                int y = pix / 24, x = pix - y*24;
                int gy = y + ky, gx = x + kx;
                int inb = ((unsigned)gy < 24u && (unsigned)gx < 24u);
                const void* src = inb
                    ? (const void*)(g_p1b + ((size_t)(img*576 + gy*24 + gx)*128 + icc*64 + ln*8))
                    : (const void*)g_p1b;
                cpa16(sb + swz((uint32_t)(r*128 + ln*16)), src, inb ? 16 : 0);
            }
            // ---- stage B (3 splits) via cp.async ----
#pragma unroll
            for (int l = 0; l < 12; l++) {
                int e = tid + l*256;
                int s = e >> 10, r = (e >> 3) & 127, ln = e & 7;
                const void* src = g_w2s + ((size_t)((s*9 + koff)*128 + r)*128 + icc*64 + ln*8);
                cpa16(sb + 16384u + (uint32_t)(s*16384) + swz((uint32_t)(r*128 + ln*16)), src, 16);
            }
            CP_COMMIT();
            CP_WAIT0();
            __syncthreads();

#pragma unroll
            for (int kk = 0; kk < 4; kk++) {
                uint32_t akb = (uint32_t)(kk*32) + a_kbsel;
                uint32_t a[2][4];
#pragma unroll
                for (int mi = 0; mi < 2; mi++)
                    ldsm4(a[mi][0], a[mi][1], a[mi][2], a[mi][3],
                          a_base[mi] + (akb ^ a_xor[mi]));
                uint32_t bkb = (uint32_t)(kk*32) + b_kbsel;
#pragma unroll
                for (int s = 0; s < 3; s++) {
                    uint32_t bs = sb + 16384u + (uint32_t)(s*16384);
#pragma unroll
                    for (int jp = 0; jp < 4; jp++) {
                        int rb = wn*64 + jp*16 + b_rl;
                        uint32_t b0, b1, b2, b3;
                        ldsm4(b0, b1, b2, b3,
                              bs + (uint32_t)(rb*128) + (bkb ^ (uint32_t)((rb & 7) << 4)));
                        hmma(acc[0][2*jp],   a[0], b0, b1);
                        hmma(acc[1][2*jp],   a[1], b0, b1);
                        hmma(acc[0][2*jp+1], a[0], b2, b3);
                        hmma(acc[1][2*jp+1], a[1], b2, b3);
                    }
                }
            }
            __syncthreads();
        }
    }

    int gid = lane >> 2, qid = lane & 3;
#pragma unroll
    for (int mi = 0; mi < 2; mi++) {
        int m = mbase + wm*32 + mi*16 + gid;
#pragma unroll
        for (int ni = 0; ni < 8; ni++) {
            int n = wn*64 + ni*8 + qid*2;
            *(float2*)(g_c2 + (size_t)m*128 + n)     = make_float2(acc[mi][ni][0], acc[mi][ni][1]);
            *(float2*)(g_c2 + (size_t)(m+8)*128 + n) = make_float2(acc[mi][ni][2], acc[mi][ni][3]);
        }
    }
}

// ============================================================
// BN2 + IF + pool -> g_s2
// ============================================================
__global__ void k_if2_pool(const float* __restrict__ b2,
                           const float* __restrict__ bg,
                           const float* __restrict__ bbta,
                           const float* __restrict__ bm,
                           const float* __restrict__ bv)
{
    int pos = blockIdx.x;
    int b = pos / 144, pp = pos % 144;
    int py = pp / 12, px = pp % 12;
    int oc = threadIdx.x;

    float scale = bg[oc] * rsqrtf(bv[oc] + 1e-5f);
    float add   = (b2[oc] - bm[oc]) * scale + bbta[oc];

    float v[4] = {0.f, 0.f, 0.f, 0.f};
#pragma unroll
    for (int t = 0; t < TT; t++) {
        float any = 0.f;
#pragma unroll
        for (int d = 0; d < 4; d++) {
            int m = (t*BB + b)*576 + (2*py + (d>>1))*24 + (2*px + (d&1));
            float xx = g_c2[(size_t)m*128 + oc] * scale + add;
            v[d] += xx;
            if (v[d] >= 1.0f) { any = 1.f; v[d] = 0.f; }
        }
        g_s2[((size_t)(t*BB + b)*144 + pp)*128 + oc] = __float2bfloat16(any);
    }
}

// ============================================================
// fc1 HMMA GEMM, split-K=16, ldmatrix + cp.async.
// ============================================================
__global__ void __launch_bounds__(256, 2) k_fc1_mma()
{
    extern __shared__ unsigned char dsm[];
    uint32_t sb0 = smaddr(dsm);
    uint32_t sb  = (sb0 + 1023) & ~1023u;
    unsigned char* sm = dsm + (sb - sb0);
    (void)sm;

    int tid = threadIdx.x, wid = tid >> 5, lane = tid & 31;
    int wm = wid & 3, wn = wid >> 2;

    int nbase = blockIdx.x * 128;
    int mbase = blockIdx.y * 128;
    int slice = blockIdx.z;
    int kbase = slice * 1152;

    int a_r[2];
    uint32_t a_base[2], a_xor[2];
#pragma unroll
    for (int mi = 0; mi < 2; mi++) {
        a_r[mi] = wm*32 + mi*16 + (lane & 15);
        a_base[mi] = sb + (uint32_t)(a_r[mi]*128);
        a_xor[mi] = (uint32_t)((a_r[mi] & 7) << 4);
    }
    uint32_t a_kbsel = (uint32_t)((lane >> 4) * 16);
    int b_rl = ((lane >> 4) & 1)*8 + (lane & 7);
    uint32_t b_kbsel = (uint32_t)(((lane >> 3) & 1) * 16);

    float acc[2][8][4];
#pragma unroll
    for (int i = 0; i < 2; i++)
#pragma unroll
        for (int j = 0; j < 8; j++)
#pragma unroll
            for (int k = 0; k < 4; k++) acc[i][j][k] = 0.f;

    for (int c = 0; c < 18; c++) {
        int k0 = kbase + c*64;
#pragma unroll
        for (int l = 0; l < 4; l++) {
            int e = tid + l*256;
            int r = e >> 3, ln = e & 7;
            const void* src = g_s2 + (size_t)(mbase + r)*FC1_IN + k0 + ln*8;
            cpa16(sb + swz((uint32_t)(r*128 + ln*16)), src, 16);
        }
#pragma unroll
        for (int l = 0; l < 12; l++) {
            int e = tid + l*256;
            int s = e >> 10, r = (e >> 3) & 127, ln = e & 7;
            const void* src = g_w1s + ((size_t)s*SZW1 + (size_t)(nbase + r)*FC1_IN + k0 + ln*8);
            cpa16(sb + 16384u + (uint32_t)(s*16384) + swz((uint32_t)(r*128 + ln*16)), src, 16);
        }
        CP_COMMIT();
        CP_WAIT0();
        __syncthreads();

#pragma unroll
        for (int kk = 0; kk < 4; kk++) {
            uint32_t akb = (uint32_t)(kk*32) + a_kbsel;
            uint32_t a[2][4];
#pragma unroll
            for (int mi = 0; mi < 2; mi++)
                ldsm4(a[mi][0], a[mi][1], a[mi][2], a[mi][3],
                      a_base[mi] + (akb ^ a_xor[mi]));
            uint32_t bkb = (uint32_t)(kk*32) + b_kbsel;
#pragma unroll
            for (int s = 0; s < 3; s++) {
                uint32_t bs = sb + 16384u + (uint32_t)(s*16384);
#pragma unroll
                for (int jp = 0; jp < 4; jp++) {
                    int rb = wn*64 + jp*16 + b_rl;
                    uint32_t b0, b1, b2, b3;
                    ldsm4(b0, b1, b2, b3,
                          bs + (uint32_t)(rb*128) + (bkb ^ (uint32_t)((rb & 7) << 4)));
                    hmma(acc[0][2*jp],   a[0], b0, b1);
                    hmma(acc[1][2*jp],   a[1], b0, b1);
                    hmma(acc[0][2*jp+1], a[0], b2, b3);
                    hmma(acc[1][2*jp+1], a[1], b2, b3);
                }
            }
        }
        __syncthreads();
    }

    int gid = lane >> 2, qid = lane & 3;
#pragma unroll
    for (int mi = 0; mi < 2; mi++) {
        int m = mbase + wm*32 + mi*16 + gid;
#pragma unroll
        for (int ni = 0; ni < 8; ni++) {
            int n = nbase + wn*64 + ni*8 + qid*2;
            float* dst = g_part1 + ((size_t)slice*NROWS + m)*FC1_OUT + n;
            *(float2*)dst = make_float2(acc[mi][ni][0], acc[mi][ni][1]);
            *(float2*)(dst + 8*FC1_OUT) = make_float2(acc[mi][ni][2], acc[mi][ni][3]);
        }
    }
}

// ============================================================
// fc2 scalar FFMA2 GEMM
// ============================================================
__global__ void __launch_bounds__(256)
k_gemm2(const float* __restrict__ Bmat, int N, int K, int klen)
{
    __shared__ float AsT[16][130];
    __shared__ float BsT[16][66];
    const float* A = g_l1;
    float* P = g_part2;

    int tid = threadIdx.x;
    int tx = tid & 15, ty = tid >> 4;
    int bm = blockIdx.y, bn = blockIdx.x, sz = blockIdx.z;
    int ks = sz * klen, ke = ks + klen;

    unsigned long long acc[4][4];
#pragma unroll
    for (int i = 0; i < 4; i++)
#pragma unroll
        for (int j = 0; j < 4; j++) acc[i][j] = 0ULL;

    for (int kk = ks; kk < ke; kk += 16) {
#pragma unroll
        for (int l = 0; l < 2; l++) {
            int lin = tid + l*256;
            int row = lin >> 2, cg = lin & 3;
            const float4 va = *reinterpret_cast<const float4*>(
                &A[(size_t)(bm*128 + row)*K + kk + cg*4]);
            AsT[cg*4 + 0][row] = va.x; AsT[cg*4 + 1][row] = va.y;
            AsT[cg*4 + 2][row] = va.z; AsT[cg*4 + 3][row] = va.w;
        }
        {
            int row = tid >> 2, cg = tid & 3;
            const float4 vb = *reinterpret_cast<const float4*>(
                &Bmat[(size_t)(bn*64 + row)*K + kk + cg*4]);
            BsT[cg*4 + 0][row] = vb.x; BsT[cg*4 + 1][row] = vb.y;
            BsT[cg*4 + 2][row] = vb.z; BsT[cg*4 + 3][row] = vb.w;
        }
        __syncthreads();
#pragma unroll
        for (int c = 0; c < 16; c++) {
            unsigned long long a2[4];
#pragma unroll
            for (int ip = 0; ip < 4; ip++)
                a2[ip] = *reinterpret_cast<const unsigned long long*>(&AsT[c][ty*8 + ip*2]);
            unsigned long long b2[4];
#pragma unroll
            for (int j = 0; j < 4; j++) {
                float bv = BsT[c][tx*4 + j];
                b2[j] = pk2(bv, bv);
            }
#pragma unroll
            for (int ip = 0; ip < 4; ip++)
#pragma unroll
                for (int j = 0; j < 4; j++)
                    acc[ip][j] = ffma2(a2[ip], b2[j], acc[ip][j]);
        }
        __syncthreads();
    }
#pragma unroll
    for (int ip = 0; ip < 4; ip++)
#pragma unroll
        for (int j = 0; j < 4; j++) {
            float2 u = upk2(acc[ip][j]);
            int row = bm*128 + ty*8 + ip*2;
            int col = bn*64 + tx*4 + j;
            P[(size_t)sz*NROWS*N + (size_t)row*N + col] = u.x;
            P[(size_t)sz*NROWS*N + (size_t)(row+1)*N + col] = u.y;
        }
}

// Deterministic split-K reduction + bias
__global__ void k_reduce_bias(const float* __restrict__ bias, int which, int N, int S)
{
    const float* P = (which == 0) ? g_part1 : g_part2;
    float* C       = (which == 0) ? g_a1 : g_a2;
    int idx = blockIdx.x * blockDim.x + threadIdx.x;
    if (idx >= NROWS*N) return;
    float s = bias[idx % N];
    for (int z = 0; z < S; z++) s += P[(size_t)z*NROWS*N + idx];
    C[idx] = s;
}

// LIF over T
__global__ void k_lif(int which, int N)
{
    const float* A = (which == 0) ? g_a1 : g_a2;
    float* L       = (which == 0) ? g_l1 : g_l2;
    int idx = blockIdx.x * blockDim.x + threadIdx.x;
    if (idx >= BB*N) return;
    int b = idx / N, o = idx % N;
    float v = 0.f;
#pragma unroll
    for (int t = 0; t < TT; t++) {
        float x = A[(size_t)(t*BB + b)*N + o];
        v += (x - v) * 0.5f;
        float s = (v >= 1.0f) ? 1.f : 0.f;
        L[(size_t)(t*BB + b)*N + o] = s;
        if (s != 0.f) v = 0.f;
    }
}

// fc3 + LIF + mean over T
__global__ void k_fc3_lif_mean(const float* __restrict__ w,
                               const float* __restrict__ bias,
                               float* __restrict__ out)
{
    __shared__ float row[FC2_OUT];
    int b = blockIdx.x, tid = threadIdx.x;
    float v = 0.f, acc = 0.f;
#pragma unroll
    for (int t = 0; t < TT; t++) {
        for (int i = tid; i < FC2_OUT; i += 32)
            row[i] = g_l2[(size_t)(t*BB + b)*FC2_OUT + i];
        __syncthreads();
        if (tid < FC3_OUT) {
            float s = bias[tid];
#pragma unroll 8
            for (int i = 0; i < FC2_OUT; i++) s += row[i] * w[tid*FC2_OUT + i];
            v += (s - v) * 0.5f;
            if (v >= 1.0f) { acc += 1.f; v = 0.f; }
        }
        __syncthreads();
    }
    if (tid < FC3_OUT) out[b*FC3_OUT + tid] = acc * 0.125f;
}

// ============================================================
extern "C" void kernel_launch(void* const* d_in, const int* in_sizes, int n_in,
                              void* d_out, int out_size)
{
    const float* x       = (const float*)d_in[0];
    const float* conv1_w = (const float*)d_in[1];
    const float* conv1_b = (const float*)d_in[2];
    const float* bn1_g   = (const float*)d_in[3];
    const float* bn1_b   = (const float*)d_in[4];
    const float* bn1_m   = (const float*)d_in[5];
    const float* bn1_v   = (const float*)d_in[6];
    const float* conv2_w = (const float*)d_in[7];
    const float* conv2_b = (const float*)d_in[8];
    const float* bn2_g   = (const float*)d_in[9];
    const float* bn2_b   = (const float*)d_in[10];
    const float* bn2_m   = (const float*)d_in[11];
    const float* bn2_v   = (const float*)d_in[12];
    const float* fc1_w   = (const float*)d_in[13];
    const float* fc1_b   = (const float*)d_in[14];
    const float* fc2_w   = (const float*)d_in[15];
    const float* fc2_b   = (const float*)d_in[16];
    const float* fc3_w   = (const float*)d_in[17];
    const float* fc3_b   = (const float*)d_in[18];
    float* out = (float*)d_out;

    const int DSM = 66560;
    cudaFuncSetAttribute(k_conv2_mma, cudaFuncAttributeMaxDynamicSharedMemorySize, DSM);
    cudaFuncSetAttribute(k_fc1_mma,  cudaFuncAttributeMaxDynamicSharedMemorySize, DSM);

    k_prep_w2<<<(128*128*9 + 255)/256, 256>>>(conv2_w);
    {
        dim3 g(FC1_OUT, 8);
        k_prep_w1<<<g, 256>>>(fc1_w);
    }
    {
        int total = BB*P1S*P1S*128;
        k_conv1_if_pool<<<(total + 255)/256, 256>>>(x, conv1_w, conv1_b,
                                                    bn1_g, bn1_b, bn1_m, bn1_v);
    }
    k_conv2_mma<<<MTOT/128, 256, DSM>>>();
    k_if2_pool<<<BB*144, 128>>>(conv2_b, bn2_g, bn2_b, bn2_m, bn2_v);
    {
        dim3 g(FC1_OUT/128, 2, 16);
        k_fc1_mma<<<g, 256, DSM>>>();
        int total = NROWS*FC1_OUT;
        k_reduce_bias<<<(total + 255)/256, 256>>>(fc1_b, 0, FC1_OUT, 16);
        int nlif = BB*FC1_OUT;
        k_lif<<<(nlif + 255)/256, 256>>>(0, FC1_OUT);
    }
    {
        dim3 g(FC2_OUT/64, NROWS/128, 8);
        k_gemm2<<<g, 256>>>(fc2_w, FC2_OUT, FC1_OUT, FC1_OUT/8);
        int total = NROWS*FC2_OUT;
        k_reduce_bias<<<(total + 255)/256, 256>>>(fc2_b, 1, FC2_OUT, 8);
        int nlif = BB*FC2_OUT;
        k_lif<<<(nlif + 255)/256, 256>>>(1, FC2_OUT);
    }
    k_fc3_lif_mean<<<BB, 32>>>(fc3_w, fc3_b, out);
}